// round 1
// baseline (speedup 1.0000x reference)
#include <cuda_runtime.h>
#include <cuda_bf16.h>

#define IMG_W 1024
#define IMG_H 1024
#define KS 15
#define NB 32

// ---- packed fp32x2 helpers (Blackwell FFMA2 path, PTX-only) ----
__device__ __forceinline__ unsigned long long pack2(float lo, float hi) {
    unsigned long long r;
    asm("mov.b64 %0, {%1, %2};" : "=l"(r) : "f"(lo), "f"(hi));
    return r;
}
__device__ __forceinline__ void unpack2(unsigned long long v, float& lo, float& hi) {
    asm("mov.b64 {%0, %1}, %2;" : "=f"(lo), "=f"(hi) : "l"(v));
}
__device__ __forceinline__ void fma2(unsigned long long& d, unsigned long long a, unsigned long long b) {
    asm("fma.rn.f32x2 %0, %1, %2, %3;" : "=l"(d) : "l"(a), "l"(b), "l"(d));
}

// Thread tile: 16 px in x, 2 rows in y. Block: 16 tx * 16 ty = 256 threads
// -> block tile 256 px (x) * 32 rows (y). Grid: (1024/256, 1024/32, B).
__global__ __launch_bounds__(256) void stem_conv_roll(
    const float* __restrict__ in, const float* __restrict__ kern,
    const int* __restrict__ shifts, float* __restrict__ out)
{
    // Padded, duplicated kernel: rows pdy = dy+1 for dy in [-1, 15]; rows 0 and 16 are zero.
    // Each entry is (w, w) packed into 8 bytes for direct f32x2 multiplier use.
    __shared__ unsigned long long sk[17 * KS];
    for (int i = threadIdx.x; i < 17 * KS; i += 256) {
        int pdy = i / KS, dx = i - pdy * KS;
        int dy = pdy - 1;
        float w = (dy >= 0 && dy < KS) ? kern[dy * KS + dx] : 0.0f;
        sk[i] = pack2(w, w);
    }
    __syncthreads();

    const int tx = threadIdx.x & 15;
    const int ty = threadIdx.x >> 4;
    const int x0 = blockIdx.x * 256 + tx * 16;   // first output px (x) of this thread
    const int oy = blockIdx.y * 32 + ty * 2;     // first output row of this thread
    const int b  = blockIdx.z;
    const float* img = in + (size_t)b * (IMG_H * IMG_W);

    unsigned long long acc[2][8];
    #pragma unroll
    for (int yy = 0; yy < 2; ++yy)
        #pragma unroll
        for (int j = 0; j < 8; ++j) acc[yy][j] = 0ull;

    // Input window per row: f[t] = in[gy][x0 - 8 + t], t = 0..31 (need t = 1..30).
    // x0 is a multiple of 16 -> (x0-8) is 16B-aligned in floats*4 bytes? (x0-8)*4 = 32 mod 64 -> 16B aligned. OK for float4.
    const int gxb = x0 - 8;
    const bool xfast = (gxb >= 0) && (gxb <= IMG_W - 32);

    for (int r = 0; r < 16; ++r) {
        const int gy = oy + r - 7;
        const bool gyok = (gy >= 0) && (gy < IMG_H);
        const float* rowp = img + (size_t)gy * IMG_W;

        float f[32];
        if (gyok && xfast) {
            #pragma unroll
            for (int v = 0; v < 8; ++v) {
                float4 t = *reinterpret_cast<const float4*>(rowp + gxb + 4 * v);
                f[4*v+0] = t.x; f[4*v+1] = t.y; f[4*v+2] = t.z; f[4*v+3] = t.w;
            }
        } else {
            #pragma unroll
            for (int e = 0; e < 32; ++e) {
                int gx = gxb + e;
                f[e] = (gyok && gx >= 0 && gx < IMG_W) ? rowp[gx] : 0.0f;
            }
        }

        // Aligned pairs pa[i] = (f[2i], f[2i+1]); offset pairs pb[i] = (f[2i+1], f[2i+2]).
        // Output pair (x0+2j, x0+2j+1), tap dx: input pair starts at f[2j+dx+1]:
        //   dx even -> pb[j + dx/2]; dx odd -> pa[j + (dx+1)/2].
        unsigned long long pa[15], pb[15];
        pa[0] = 0ull;
        #pragma unroll
        for (int i = 1; i < 15; ++i) pa[i] = pack2(f[2*i], f[2*i+1]);
        #pragma unroll
        for (int i = 0; i < 15; ++i) pb[i] = pack2(f[2*i+1], f[2*i+2]);

        #pragma unroll
        for (int yy = 0; yy < 2; ++yy) {
            // dy = r - yy; padded row index pdy = dy + 1 (zero rows absorb out-of-range dy)
            const unsigned long long* kr = &sk[(r - yy + 1) * KS];
            #pragma unroll
            for (int dx = 0; dx < KS; ++dx) {
                unsigned long long kw = kr[dx];
                if (dx & 1) {
                    #pragma unroll
                    for (int j = 0; j < 8; ++j) fma2(acc[yy][j], pa[j + (dx + 1) / 2], kw);
                } else {
                    #pragma unroll
                    for (int j = 0; j < 8; ++j) fma2(acc[yy][j], pb[j + dx / 2], kw);
                }
            }
        }
    }

    // Fused roll: out[b, y, (x + s) mod W] = conv[b, y, x]. W = 1024 (pow2).
    #pragma unroll
    for (int yy = 0; yy < 2; ++yy) {
        const int y = oy + yy;
        const int s = shifts[b * IMG_H + y];
        float* orow = out + ((size_t)b * IMG_H + y) * IMG_W;
        if ((s & 1) == 0) {
            // even shift: destination pair stays 8B-aligned and never straddles the wrap
            #pragma unroll
            for (int j = 0; j < 8; ++j) {
                int c = (x0 + 2 * j + s) & (IMG_W - 1);
                float lo, hi; unpack2(acc[yy][j], lo, hi);
                *reinterpret_cast<float2*>(orow + c) = make_float2(lo, hi);
            }
        } else {
            #pragma unroll
            for (int j = 0; j < 8; ++j) {
                float lo, hi; unpack2(acc[yy][j], lo, hi);
                int c0 = (x0 + 2 * j + s) & (IMG_W - 1);
                orow[c0] = lo;
                orow[(c0 + 1) & (IMG_W - 1)] = hi;
            }
        }
    }
}

extern "C" void kernel_launch(void* const* d_in, const int* in_sizes, int n_in,
                              void* d_out, int out_size) {
    const float* img = nullptr;
    const float* kern = nullptr;
    const int*   shifts = nullptr;
    for (int i = 0; i < n_in; ++i) {
        if (in_sizes[i] == NB * IMG_H * IMG_W)      img    = (const float*)d_in[i];
        else if (in_sizes[i] == KS * KS)            kern   = (const float*)d_in[i];
        else if (in_sizes[i] == NB * IMG_H)         shifts = (const int*)d_in[i];
    }
    dim3 grid(IMG_W / 256, IMG_H / 32, NB);
    stem_conv_roll<<<grid, 256>>>(img, kern, shifts, (float*)d_out);
}

// round 2
// speedup vs baseline: 1.4411x; 1.4411x over previous
#include <cuda_runtime.h>
#include <cuda_bf16.h>

#define IMG_W 1024
#define IMG_H 1024
#define KS 15
#define NB 32

typedef unsigned long long u64;

// ---- packed fp32x2 helpers (Blackwell, PTX-only) ----
__device__ __forceinline__ u64 pack2(float lo, float hi) {
    u64 r;
    asm("mov.b64 %0, {%1, %2};" : "=l"(r) : "f"(lo), "f"(hi));
    return r;
}
__device__ __forceinline__ void unpack2(u64 v, float& lo, float& hi) {
    asm("mov.b64 {%0, %1}, %2;" : "=f"(lo), "=f"(hi) : "l"(v));
}
__device__ __forceinline__ void fma2(u64& d, u64 a, u64 b) {
    asm("fma.rn.f32x2 %0, %1, %2, %3;" : "=l"(d) : "l"(a), "l"(b), "l"(d));
}
__device__ __forceinline__ u64 add2(u64 a, u64 b) {
    u64 r;
    asm("add.rn.f32x2 %0, %1, %2;" : "=l"(r) : "l"(a), "l"(b));
    return r;
}

// Thread: 2 px (one f32x2 pair) x 8 output rows. Lanes x-contiguous:
// warp covers 64 consecutive px. Block 256 thr = 8 warps: 2 in x, 4 in y.
// Block tile: 128 px (x) * 32 rows (y). Grid (8, 32, 32).
__global__ __launch_bounds__(256) void stem_conv_roll(
    const float* __restrict__ in, const float* __restrict__ kern,
    const int* __restrict__ shifts, float* __restrict__ out)
{
    // Folded weights: sk[dy*8 + e] = (w,w) with w = k[dy][7+e] (e=0 -> center).
    // Airy kernel is exactly symmetric in dx, so k[dy][7-e] == k[dy][7+e].
    __shared__ u64 sk[KS * 8];
    for (int i = threadIdx.x; i < KS * 8; i += 256) {
        int dy = i >> 3, e = i & 7;
        float w = kern[dy * KS + 7 + e];
        sk[i] = pack2(w, w);
    }
    __syncthreads();

    const int lane = threadIdx.x & 31;
    const int warp = threadIdx.x >> 5;
    const int wx = warp & 1;
    const int wy = warp >> 1;
    const int x0 = blockIdx.x * 128 + wx * 64 + lane * 2;  // even
    const int y0 = blockIdx.y * 32 + wy * 8;
    const int b  = blockIdx.z;
    const float* img = in + (size_t)b * (IMG_H * IMG_W);

    u64 acc[8];
    #pragma unroll
    for (int r = 0; r < 8; ++r) acc[r] = 0ull;

    // Need in[gy][x0-8 .. x0+9] = ga[0..17] (ga[j] = in[gy][x0-8+j]); x0 even
    // so float2 loads at x0-8 are 8B-aligned.
    const bool xfast = (x0 >= 8) && (x0 <= IMG_W - 10);

    #pragma unroll
    for (int g = 0; g < 22; ++g) {
        const int gy = y0 - 7 + g;
        if (gy >= 0 && gy < IMG_H) {                 // uniform across warp
            const float* rowp = img + (size_t)gy * IMG_W;
            float ga[18];
            if (xfast) {
                #pragma unroll
                for (int i = 0; i < 9; ++i) {
                    float2 t = *reinterpret_cast<const float2*>(rowp + x0 - 8 + 2 * i);
                    ga[2 * i] = t.x; ga[2 * i + 1] = t.y;
                }
            } else {
                #pragma unroll
                for (int j = 0; j < 18; ++j) {
                    int gx = x0 - 8 + j;
                    ga[j] = (gx >= 0 && gx < IMG_W) ? rowp[gx] : 0.0f;
                }
            }

            // Horizontal fold: h[e] = (in[x0-e]+in[x0+e], in[x0+1-e]+in[x0+1+e]).
            // Even e: add2 of two naturally-aligned loaded pairs (no repacking).
            // Odd e: scalar FADDs written straight into a pair.
            u64 h[8];
            h[0] = pack2(ga[8], ga[9]);
            h[1] = pack2(ga[7] + ga[9],  ga[8] + ga[10]);
            h[2] = add2(pack2(ga[6],  ga[7]),  pack2(ga[10], ga[11]));
            h[3] = pack2(ga[5] + ga[11], ga[6] + ga[12]);
            h[4] = add2(pack2(ga[4],  ga[5]),  pack2(ga[12], ga[13]));
            h[5] = pack2(ga[3] + ga[13], ga[4] + ga[14]);
            h[6] = add2(pack2(ga[2],  ga[3]),  pack2(ga[14], ga[15]));
            h[7] = pack2(ga[1] + ga[15], ga[2] + ga[16]);

            // Input row gy contributes to output row y0+r with dy = g - r in [0,14].
            #pragma unroll
            for (int r = 0; r < 8; ++r) {
                if (r >= g - 14 && r <= g) {   // compile-time after unroll
                    const u64* kw = &sk[(g - r) * 8];
                    ulonglong2 w01 = *reinterpret_cast<const ulonglong2*>(kw + 0);
                    ulonglong2 w23 = *reinterpret_cast<const ulonglong2*>(kw + 2);
                    ulonglong2 w45 = *reinterpret_cast<const ulonglong2*>(kw + 4);
                    ulonglong2 w67 = *reinterpret_cast<const ulonglong2*>(kw + 6);
                    fma2(acc[r], h[0], w01.x);
                    fma2(acc[r], h[1], w01.y);
                    fma2(acc[r], h[2], w23.x);
                    fma2(acc[r], h[3], w23.y);
                    fma2(acc[r], h[4], w45.x);
                    fma2(acc[r], h[5], w45.y);
                    fma2(acc[r], h[6], w67.x);
                    fma2(acc[r], h[7], w67.y);
                }
            }
        }
    }

    // Fused roll: out[b, y, (x + s) & 1023] = conv[b, y, x].
    #pragma unroll
    for (int r = 0; r < 8; ++r) {
        const int y = y0 + r;
        const int s = shifts[b * IMG_H + y];
        float* orow = out + ((size_t)b * IMG_H + y) * IMG_W;
        float lo, hi; unpack2(acc[r], lo, hi);
        int c = (x0 + s) & (IMG_W - 1);
        if ((s & 1) == 0) {
            // even shift: c even -> aligned float2, never straddles the wrap
            *reinterpret_cast<float2*>(orow + c) = make_float2(lo, hi);
        } else {
            orow[c] = lo;
            orow[(c + 1) & (IMG_W - 1)] = hi;
        }
    }
}

extern "C" void kernel_launch(void* const* d_in, const int* in_sizes, int n_in,
                              void* d_out, int out_size) {
    const float* img = nullptr;
    const float* kern = nullptr;
    const int*   shifts = nullptr;
    for (int i = 0; i < n_in; ++i) {
        if (in_sizes[i] == NB * IMG_H * IMG_W)      img    = (const float*)d_in[i];
        else if (in_sizes[i] == KS * KS)            kern   = (const float*)d_in[i];
        else if (in_sizes[i] == NB * IMG_H)         shifts = (const int*)d_in[i];
    }
    dim3 grid(IMG_W / 128, IMG_H / 32, NB);
    stem_conv_roll<<<grid, 256>>>(img, kern, shifts, (float*)d_out);
}